// round 6
// baseline (speedup 1.0000x reference)
#include <cuda_runtime.h>
#include <math.h>
#include <stdint.h>

#define CIN_   128
#define COUT_  256
#define NB     16
#define HW_    56
#define NPIX   3136
#define WPAD   58
#define RPB    3480            /* 60*58 padded rows per batch */
#define M_TOTAL 55680
#define M_ALLOC 55808
#define KDIM   2304            /* 9 taps * 256 (cos/sin x 128ch) */
#define NDIM   512             /* 2 (re/im) * 256 couts */

#define MT 128
#define NT 64
#define NITER 72               /* 9 taps * 8 k-chunks of 32 */
#define STAGES 4
#define NTHR 256

#define NLIMB 4
#define ROWSTRIDE 144                   /* 128B data (4 limbs x 32B) + 16B pad */
#define ABYTES (128 * ROWSTRIDE)        /* 18432 */
#define BBYTES (64 * ROWSTRIDE)         /* 9216 */
#define STG_BYTES (ABYTES + BBYTES)     /* 27648 */
#define SMEM_DYN (STAGES * STG_BYTES)   /* 110592 */

#define APLANE ((size_t)M_ALLOC * 256)
#define BPLANE ((size_t)NDIM * KDIM)

/* scratch: zero-initialized device globals (padding rows read as 0) */
static __device__ char g_A[NLIMB * APLANE];   /* limb planes: [4][M_ALLOC][256] */
static __device__ char g_B[NLIMB * BPLANE];   /* [4][NDIM][KDIM] */

__device__ __forceinline__ void cpa16(uint32_t dst, const void* src) {
    asm volatile("cp.async.cg.shared.global [%0], [%1], 16;" :: "r"(dst), "l"(src) : "memory");
}
#define LDSM4(R, A) \
    asm volatile("ldmatrix.sync.aligned.m8n8.x4.shared.b16 {%0,%1,%2,%3}, [%4];" \
                 : "=r"((R)[0]), "=r"((R)[1]), "=r"((R)[2]), "=r"((R)[3]) : "r"(A))
#define LDSM2(R, A) \
    asm volatile("ldmatrix.sync.aligned.m8n8.x2.shared.b16 {%0,%1}, [%2];" \
                 : "=r"((R)[0]), "=r"((R)[1]) : "r"(A))
#define IMMA(C, A, B) \
    asm volatile("mma.sync.aligned.m16n8k32.row.col.s32.s8.s8.s32 " \
                 "{%0,%1,%2,%3}, {%4,%5,%6,%7}, {%8,%9}, {%0,%1,%2,%3};" \
                 : "+r"((C)[0]), "+r"((C)[1]), "+r"((C)[2]), "+r"((C)[3]) \
                 : "r"((A)[0]), "r"((A)[1]), "r"((A)[2]), "r"((A)[3]), \
                   "r"((B)[0]), "r"((B)[1]))

/* 4-limb exact split: v = q0/2^6 + q1/2^13 + q2/2^20 + q3/2^27 + d, |d|<=2^-28.
   All residual subtractions are exact in fp32. */
__device__ __forceinline__ void quant4(float v, char* q) {
    float s = v * 64.0f;
    int l0 = __float2int_rn(s);
    float r1 = (s - (float)l0) * 128.0f;
    int l1 = __float2int_rn(r1);
    float r2 = (r1 - (float)l1) * 128.0f;
    int l2 = __float2int_rn(r2);
    float r3 = (r2 - (float)l2) * 128.0f;
    int l3 = __float2int_rn(r3);
    q[0] = (char)l0; q[1] = (char)l1; q[2] = (char)l2; q[3] = (char)l3;
}

/* ---------------- prep kernels ---------------- */

__global__ void prep_w(const float* __restrict__ probe, const float* __restrict__ oang) {
    int idx = blockIdx.x * blockDim.x + threadIdx.x;
    if (idx >= NDIM * KDIM) return;
    int n = idx / KDIM, k = idx - n * KDIM;
    int tap = k >> 8, c = k & 255;
    int ci = c >> 1, s = c & 1;
    int co = n >> 1, r = n & 1;
    int pidx = ci * 2304 + co * 9 + tap;          /* (1,CIN,COUT,1,1,3,3) flat */
    float p = probe[pidx], o = oang[pidx];
    float sp, cp, so, cco;
    sincosf(p, &sp, &cp);
    sincosf(o, &so, &cco);
    float v = (s ? sp : cp) * (r ? so : cco);
    char q[4];
    quant4(v, q);
#pragma unroll
    for (int L = 0; L < NLIMB; L++)
        g_B[(size_t)L * BPLANE + idx] = q[L];
}

__global__ void prep_in(const float* __restrict__ x) {
    int idx = blockIdx.x * blockDim.x + threadIdx.x;
    if (idx >= NB * NPIX * CIN_) return;
    int ci = idx & 127;
    int t  = idx >> 7;
    int b  = t / NPIX;
    int p  = t - b * NPIX;
    int h  = p / HW_, w = p - h * HW_;
    float v = x[((size_t)(b * CIN_ + ci)) * NPIX + p];
    float sv, cv;
    sincosf(v, &sv, &cv);
    size_t base = ((size_t)b * RPB + (h + 1) * WPAD + (w + 1)) * 256 + 2 * ci;
    char qc[4], qs[4];
    quant4(cv, qc);
    quant4(sv, qs);
#pragma unroll
    for (int L = 0; L < NLIMB; L++) {
        g_A[(size_t)L * APLANE + base]     = qc[L];
        g_A[(size_t)L * APLANE + base + 1] = qs[L];
    }
}

/* ---------------- main IMMA kernel ---------------- */

__global__ __launch_bounds__(NTHR, 1) void ring_imma(float* __restrict__ out) {
    extern __shared__ char smem[];
    const uint32_t sb = (uint32_t)__cvta_generic_to_shared(smem);
    const int tid = threadIdx.x;
    const int lane = tid & 31, wid = tid >> 5;
    const int warp_m = wid & 3;          /* 4 warps over M: 32 rows each */
    const int warp_n = wid >> 2;         /* 2 warps over N: 32 cols each */
    const int m0 = blockIdx.x * MT;
    const int n0 = blockIdx.y * NT;

    /* acc[s][f][g][j]: s = limb-scale set (2^0, 2^-7, 2^-14, 2^-21) */
    int acc[4][2][4][4];
#pragma unroll
    for (int s = 0; s < 4; s++)
#pragma unroll
        for (int f = 0; f < 2; f++)
#pragma unroll
            for (int g = 0; g < 4; g++)
#pragma unroll
                for (int j = 0; j < 4; j++) acc[s][f][g][j] = 0;

    uint32_t a_off[2], b_off[4];
#pragma unroll
    for (int f = 0; f < 2; f++)
        a_off[f] = (uint32_t)((warp_m * 32 + f * 16 + (lane & 15)) * ROWSTRIDE
                              + ((lane >> 4) ? 16 : 0));
#pragma unroll
    for (int g = 0; g < 4; g++)
        b_off[g] = (uint32_t)(ABYTES + (warp_n * 32 + g * 8 + (lane & 7)) * ROWSTRIDE
                              + ((lane & 8) ? 16 : 0));

    auto load_stage = [&](int it, int sg) {
        const int tap = it >> 3, kc = it & 7;
        const int arow0 = m0 + (tap / 3) * WPAD + (tap % 3);
        const int kbA = kc * 32;
        const int kbB = tap * 256 + kc * 32;
        const uint32_t st = sb + (uint32_t)sg * STG_BYTES;
#pragma unroll
        for (int u = 0; u < 6; u++) {
            int idx = u * NTHR + tid;              /* 0..1535 */
            if (idx < 1024) {                      /* A: 128 rows x 8 chunks */
                int r = idx >> 3, c = idx & 7;
                int limb = c >> 1, seg = c & 1;
                uint32_t d = st + (uint32_t)(r * ROWSTRIDE + limb * 32 + seg * 16);
                cpa16(d, g_A + (size_t)limb * APLANE
                            + (size_t)(arow0 + r) * 256 + kbA + seg * 16);
            } else {                               /* B: 64 rows x 8 chunks */
                int j = idx - 1024;
                int r = j >> 3, c = j & 7;
                int limb = c >> 1, seg = c & 1;
                uint32_t d = st + (uint32_t)(ABYTES + r * ROWSTRIDE + limb * 32 + seg * 16);
                cpa16(d, g_B + (size_t)limb * BPLANE
                            + (size_t)(n0 + r) * KDIM + kbB + seg * 16);
            }
        }
    };

#pragma unroll
    for (int p = 0; p < STAGES - 1; p++) {
        load_stage(p, p);
        asm volatile("cp.async.commit_group;" ::: "memory");
    }

#pragma unroll 1
    for (int it = 0; it < NITER; it++) {
        const int pf = it + STAGES - 1;
        if (pf < NITER) load_stage(pf, pf & 3);
        asm volatile("cp.async.commit_group;" ::: "memory");
        asm volatile("cp.async.wait_group 3;" ::: "memory");
        __syncthreads();

        const uint32_t st = sb + (uint32_t)(it & 3) * STG_BYTES;

        /* all B limb fragments resident; A limbs streamed (each used once) */
        uint32_t Bf[4][4][2];
#pragma unroll
        for (int L = 0; L < 4; L++)
#pragma unroll
            for (int g = 0; g < 4; g++)
                LDSM2(Bf[L][g], st + b_off[g] + L * 32);

#pragma unroll
        for (int L = 0; L < 4; L++) {
            uint32_t Af[2][4];
#pragma unroll
            for (int f = 0; f < 2; f++)
                LDSM4(Af[f], st + a_off[f] + L * 32);
#pragma unroll
            for (int f = 0; f < 2; f++)
#pragma unroll
                for (int g = 0; g < 4; g++)
#pragma unroll
                    for (int j = 0; j < 4 - L; j++)
                        IMMA(acc[L + j][f][g], Af[f], Bf[j][g]);
        }
        __syncthreads();
    }

    /* epilogue: double-precision limb combine -> atan2 -> smem transpose -> store */
    float* eb = (float*)smem + wid * 512;       /* 16 couts x 32 rows per warp */
    const int lm = lane >> 2, ln = lane & 3;
#pragma unroll
    for (int f = 0; f < 2; f++)
#pragma unroll
        for (int g = 0; g < 4; g++)
#pragma unroll
            for (int h = 0; h < 2; h++) {
                double re = 2097152.0 * (double)acc[0][f][g][2 * h]
                          +   16384.0 * (double)acc[1][f][g][2 * h]
                          +     128.0 * (double)acc[2][f][g][2 * h]
                          +            (double)acc[3][f][g][2 * h];
                double im = 2097152.0 * (double)acc[0][f][g][2 * h + 1]
                          +   16384.0 * (double)acc[1][f][g][2 * h + 1]
                          +     128.0 * (double)acc[2][f][g][2 * h + 1]
                          +            (double)acc[3][f][g][2 * h + 1];
                int row = f * 16 + h * 8 + lm;
                int cl  = g * 4 + ln;
                eb[cl * 32 + row] = atan2f((float)im, (float)re);
            }
    __syncwarp();

    const int co_base = (n0 >> 1) + warp_n * 16;
    const int mbase = m0 + warp_m * 32;
#pragma unroll 1
    for (int i = 0; i < 16; i++) {
        int idx = i * 32 + lane;
        int cl = idx >> 5, r = idx & 31;
        int m = mbase + r;
        int b = m / RPB;
        int rem = m - b * RPB;
        int h = rem / WPAD, w = rem - h * WPAD;
        if (h < HW_ && w < HW_)
            out[((size_t)(b * COUT_ + co_base + cl)) * NPIX + h * HW_ + w] =
                eb[cl * 32 + r];
    }
}

/* ---------------- launch ---------------- */

extern "C" void kernel_launch(void* const* d_in, const int* in_sizes, int n_in,
                              void* d_out, int out_size) {
    const float* x     = (const float*)d_in[0];
    const float* probe = (const float*)d_in[1];
    const float* oang  = (const float*)d_in[2];
    float* out = (float*)d_out;

    cudaFuncSetAttribute(ring_imma, cudaFuncAttributeMaxDynamicSharedMemorySize, SMEM_DYN);

    prep_w<<<(NDIM * KDIM + 255) / 256, 256>>>(probe, oang);
    prep_in<<<(NB * NPIX * CIN_ + 255) / 256, 256>>>(x);

    dim3 grid(M_TOTAL / MT, NDIM / NT, 1);      /* (435, 8) */
    ring_imma<<<grid, NTHR, SMEM_DYN>>>(out);
}

// round 7
// speedup vs baseline: 7.7772x; 7.7772x over previous
#include <cuda_runtime.h>
#include <math.h>

// Problem constants
#define B_    16
#define CIN   128
#define COUT  256
#define HW    56
#define HWHW  (HW*HW)        // 3136
#define KTAPS 9

// Tiling (identical to the validated R2 fp32 kernel)
#define CI_T    8
#define COUT_T  32
#define TH      8
#define TW      8
#define HALO    10
#define NTHREADS 128

typedef unsigned long long u64;

// weights packed for f32x2: w = (wx, wz, wy, ww) = (cp*co, cp*so, sp*co, sp*so)
//   .xy = pair applied to cos(x)  [re, im lanes]
//   .zw = pair applied to sin(x)
static __device__ float4 g_w[CIN * KTAPS * COUT];             // 4.7 MB
static __device__ float2 g_cs[B_ * CIN * HWHW];               // 51.4 MB

__device__ __forceinline__ void fma2(u64& acc, u64 a, u64 b) {
    asm("fma.rn.f32x2 %0, %1, %2, %0;" : "+l"(acc) : "l"(a), "l"(b));
}
__device__ __forceinline__ u64 bcast2(float v) {
    u64 r;
    asm("mov.b64 %0, {%1, %1};" : "=l"(r) : "f"(v));
    return r;
}
__device__ __forceinline__ u64 pack2(float lo, float hi) {
    u64 r;
    asm("mov.b64 %0, {%1, %2};" : "=l"(r) : "f"(lo), "f"(hi));
    return r;
}
__device__ __forceinline__ void unpack2(u64 v, float& lo, float& hi) {
    asm("mov.b64 {%0, %1}, %2;" : "=f"(lo), "=f"(hi) : "l"(v));
}

__global__ void prep_weights_kernel(const float* __restrict__ probe,
                                    const float* __restrict__ outang) {
    int idx = blockIdx.x * blockDim.x + threadIdx.x;
    int n = CIN * COUT * KTAPS;
    if (idx >= n) return;
    int tap = idx % KTAPS;
    int co  = (idx / KTAPS) % COUT;
    int ci  = idx / (KTAPS * COUT);
    float p = probe[idx];
    float o = outang[idx];
    float cp, sp, c_o, s_o;
    sincosf(p, &sp, &cp);
    sincosf(o, &s_o, &c_o);
    // (wx, wz, wy, ww)
    g_w[(ci * KTAPS + tap) * COUT + co] =
        make_float4(cp * c_o, cp * s_o, sp * c_o, sp * s_o);
}

__global__ void prep_input_kernel(const float* __restrict__ x) {
    int idx = blockIdx.x * blockDim.x + threadIdx.x;
    if (idx >= B_ * CIN * HWHW) return;
    float v = x[idx];
    float s, c;
    sincosf(v, &s, &c);
    g_cs[idx] = make_float2(c, s);
}

// Direct conv with packed dual-fp32 accumulators.
// Grid: (49 spatial tiles, 8 cout blocks, 16 batches).
// Block: 32 couts x 64 pixels. Thread: 4 couts x 4 pixels (2x2).
__global__ __launch_bounds__(NTHREADS)
void ring_conv_kernel(float* __restrict__ out) {
    __shared__ float4 sW[CI_T][KTAPS][COUT_T];   // 36,864 B
    __shared__ float2 sI[CI_T][HALO][HALO];      //  6,400 B

    const int tid = threadIdx.x;
    const int tile = blockIdx.x;
    const int th = tile / 7, tw = tile % 7;
    const int cb = blockIdx.y * COUT_T;
    const int b  = blockIdx.z;
    const int h0 = th * TH - 1, w0 = tw * TW - 1;

    const int pg  = tid & 15;
    const int cg  = tid >> 4;
    const int pgh = pg >> 2, pgw = pg & 3;

    u64 acc[4][4];                    // packed (re, im)
#pragma unroll
    for (int p = 0; p < 4; p++)
#pragma unroll
        for (int j = 0; j < 4; j++) acc[p][j] = 0ULL;

    const float2* __restrict__ csb = g_cs + (size_t)b * CIN * HWHW;

    for (int ci0 = 0; ci0 < CIN; ci0 += CI_T) {
        __syncthreads();
#pragma unroll
        for (int idx = tid; idx < CI_T * KTAPS * COUT_T; idx += NTHREADS) {
            int ci_l = idx / (KTAPS * COUT_T);
            int rem  = idx % (KTAPS * COUT_T);
            int tap  = rem / COUT_T;
            int col  = rem % COUT_T;
            sW[ci_l][tap][col] = g_w[((ci0 + ci_l) * KTAPS + tap) * COUT + cb + col];
        }
#pragma unroll
        for (int idx = tid; idx < CI_T * HALO * HALO; idx += NTHREADS) {
            int ci_l = idx / (HALO * HALO);
            int rem  = idx % (HALO * HALO);
            int r = rem / HALO, c = rem % HALO;
            int h = h0 + r, w = w0 + c;
            float2 v = make_float2(0.f, 0.f);
            if ((unsigned)h < HW && (unsigned)w < HW)
                v = csb[(ci0 + ci_l) * HWHW + h * HW + w];
            sI[ci_l][r][c] = v;
        }
        __syncthreads();

        for (int ci_l = 0; ci_l < CI_T; ci_l++) {
#pragma unroll
            for (int kh = 0; kh < 3; kh++) {
#pragma unroll
                for (int kw = 0; kw < 3; kw++) {
                    // broadcast-packed inputs for 4 pixels
                    u64 xx[4], yy[4];
#pragma unroll
                    for (int p = 0; p < 4; p++) {
                        float2 iv = sI[ci_l][pgh * 2 + kh + (p >> 1)]
                                          [pgw * 2 + kw + (p & 1)];
                        xx[p] = bcast2(iv.x);
                        yy[p] = bcast2(iv.y);
                    }
#pragma unroll
                    for (int j = 0; j < 4; j++) {
                        float4 w4 = sW[ci_l][kh * 3 + kw][cg * 4 + j];
                        u64 wc = pack2(w4.x, w4.y);   // (wx, wz): applies to cos
                        u64 ws = pack2(w4.z, w4.w);   // (wy, ww): applies to sin
#pragma unroll
                        for (int p = 0; p < 4; p++) {
                            fma2(acc[p][j], xx[p], wc);
                            fma2(acc[p][j], yy[p], ws);
                        }
                    }
                }
            }
        }
    }

    // epilogue: unpack, atan2, store
    const int hh = th * TH + pgh * 2;
    const int ww = tw * TW + pgw * 2;
#pragma unroll
    for (int p = 0; p < 4; p++) {
        int h = hh + (p >> 1), w = ww + (p & 1);
#pragma unroll
        for (int j = 0; j < 4; j++) {
            int co = cb + cg * 4 + j;
            float re, im;
            unpack2(acc[p][j], re, im);
            out[((size_t)b * COUT + co) * HWHW + h * HW + w] = atan2f(im, re);
        }
    }
}

extern "C" void kernel_launch(void* const* d_in, const int* in_sizes, int n_in,
                              void* d_out, int out_size) {
    const float* x     = (const float*)d_in[0];
    const float* probe = (const float*)d_in[1];
    const float* oang  = (const float*)d_in[2];
    float* out = (float*)d_out;

    {
        int n = CIN * COUT * KTAPS;
        prep_weights_kernel<<<(n + 255) / 256, 256>>>(probe, oang);
    }
    {
        int n = B_ * CIN * HWHW;
        prep_input_kernel<<<(n + 255) / 256, 256>>>(x);
    }
    {
        dim3 grid(49, COUT / COUT_T, B_);
        ring_conv_kernel<<<grid, NTHREADS>>>(out);
    }
}

// round 9
// speedup vs baseline: 15.1148x; 1.9435x over previous
#include <cuda_runtime.h>
#include <math.h>

#define B_    16
#define CIN   128
#define COUT  256
#define HW    56
#define HWHW  3136
#define TILES 784            /* 28x28 per image */
#define MW    12544          /* 16*784 total tiles  (GEMM M) */
#define KW    256            /* 2*CIN cos/sin       (GEMM K) */
#define NW    256            /* couts, f32x2-packed (GEMM N) */

#define BM 64
#define BN 64
#define BK 16
#define NKT (KW/BK)          /* 16 */
#define GTH 128

typedef unsigned long long u64;

/* device scratch (zero-init) */
static __device__ float2 g_cs[(size_t)B_ * CIN * HWHW];        /*  51 MB */
static __device__ float  g_V[(size_t)16 * KW * MW];            /* 205 MB */
static __device__ u64    g_U[(size_t)16 * KW * NW];            /* 8.4 MB */
static __device__ u64    g_M[(size_t)16 * NW * MW];            /* 411 MB */

__device__ __forceinline__ void fma2(u64& acc, u64 a, u64 b) {
    asm("fma.rn.f32x2 %0, %1, %2, %0;" : "+l"(acc) : "l"(a), "l"(b));
}
__device__ __forceinline__ u64 add2(u64 a, u64 b) {
    u64 r; asm("add.rn.f32x2 %0, %1, %2;" : "=l"(r) : "l"(a), "l"(b)); return r;
}
__device__ __forceinline__ u64 sub2(u64 a, u64 b) {
    u64 r; asm("sub.rn.f32x2 %0, %1, %2;" : "=l"(r) : "l"(a), "l"(b)); return r;
}
__device__ __forceinline__ u64 bcast2(float v) {
    u64 r; asm("mov.b64 %0, {%1, %1};" : "=l"(r) : "f"(v)); return r;
}
__device__ __forceinline__ u64 pack2(float lo, float hi) {
    u64 r; asm("mov.b64 %0, {%1, %2};" : "=l"(r) : "f"(lo), "f"(hi)); return r;
}
__device__ __forceinline__ void unpack2(u64 v, float& lo, float& hi) {
    asm("mov.b64 {%0, %1}, %2;" : "=f"(lo), "=f"(hi) : "l"(v));
}
__device__ __forceinline__ void cpa16(void* dst, const void* src) {
    unsigned d = (unsigned)__cvta_generic_to_shared(dst);
    asm volatile("cp.async.cg.shared.global [%0], [%1], 16;" :: "r"(d), "l"(src) : "memory");
}

/* ---------- prep: sincos of x ---------- */
__global__ void prep_input_kernel(const float* __restrict__ x) {
    int idx = blockIdx.x * blockDim.x + threadIdx.x;
    if (idx >= B_ * CIN * HWHW) return;
    float s, c;
    sincosf(x[idx], &s, &c);
    g_cs[idx] = make_float2(c, s);
}

/* ---------- weight transform: U = G g G^T, packed (re,im) ---------- */
__global__ void wino_wprep(const float* __restrict__ probe,
                           const float* __restrict__ oang) {
    int idx = blockIdx.x * blockDim.x + threadIdx.x;   /* 256*256 */
    int co = idx & 255;
    int c  = idx >> 8;             /* cin2: 2*ci + s */
    int ci = c >> 1, s = c & 1;
    float gre[3][3], gim[3][3];
#pragma unroll
    for (int tap = 0; tap < 9; tap++) {
        int pidx = ci * 2304 + co * 9 + tap;
        float p = probe[pidx], o = oang[pidx];
        float sp, cp, so, c_o;
        sincosf(p, &sp, &cp);
        sincosf(o, &so, &c_o);
        float a = s ? sp : cp;
        gre[tap / 3][tap % 3] = a * c_o;
        gim[tap / 3][tap % 3] = a * so;
    }
    float Ur[4][4], Ui[4][4];
    {
        float t[4][3];
#pragma unroll
        for (int j = 0; j < 3; j++) {
            t[0][j] = gre[0][j];
            t[1][j] = 0.5f * (gre[0][j] + gre[1][j] + gre[2][j]);
            t[2][j] = 0.5f * (gre[0][j] - gre[1][j] + gre[2][j]);
            t[3][j] = gre[2][j];
        }
#pragma unroll
        for (int i = 0; i < 4; i++) {
            Ur[i][0] = t[i][0];
            Ur[i][1] = 0.5f * (t[i][0] + t[i][1] + t[i][2]);
            Ur[i][2] = 0.5f * (t[i][0] - t[i][1] + t[i][2]);
            Ur[i][3] = t[i][2];
        }
    }
    {
        float t[4][3];
#pragma unroll
        for (int j = 0; j < 3; j++) {
            t[0][j] = gim[0][j];
            t[1][j] = 0.5f * (gim[0][j] + gim[1][j] + gim[2][j]);
            t[2][j] = 0.5f * (gim[0][j] - gim[1][j] + gim[2][j]);
            t[3][j] = gim[2][j];
        }
#pragma unroll
        for (int i = 0; i < 4; i++) {
            Ui[i][0] = t[i][0];
            Ui[i][1] = 0.5f * (t[i][0] + t[i][1] + t[i][2]);
            Ui[i][2] = 0.5f * (t[i][0] - t[i][1] + t[i][2]);
            Ui[i][3] = t[i][2];
        }
    }
#pragma unroll
    for (int i = 0; i < 4; i++)
#pragma unroll
        for (int j = 0; j < 4; j++)
            g_U[(size_t)(i * 4 + j) * KW * NW + (size_t)c * NW + co] =
                pack2(Ur[i][j], Ui[i][j]);
}

/* ---------- input transform: V = B^T d B ---------- */
__global__ void wino_vprep() {
    int m  = blockIdx.x * 256 + threadIdx.x;   /* grid.x = 49 */
    int ci = blockIdx.y;                       /* 0..127 */
    int b  = m / TILES;
    int t  = m - b * TILES;
    int ty = t / 28, tx = t - (t / 28) * 28;
    const float2* plane = g_cs + ((size_t)b * CIN + ci) * HWHW;
    float dc[4][4], ds[4][4];
#pragma unroll
    for (int i = 0; i < 4; i++) {
        int r = 2 * ty - 1 + i;
#pragma unroll
        for (int j = 0; j < 4; j++) {
            int cc = 2 * tx - 1 + j;
            float2 v = make_float2(0.f, 0.f);
            if ((unsigned)r < HW && (unsigned)cc < HW) v = plane[r * HW + cc];
            dc[i][j] = v.x; ds[i][j] = v.y;
        }
    }
    float Vc[4][4], Vs[4][4];
    {
        float tt[4][4];
#pragma unroll
        for (int j = 0; j < 4; j++) {
            tt[0][j] = dc[0][j] - dc[2][j];
            tt[1][j] = dc[1][j] + dc[2][j];
            tt[2][j] = dc[2][j] - dc[1][j];
            tt[3][j] = dc[1][j] - dc[3][j];
        }
#pragma unroll
        for (int i = 0; i < 4; i++) {
            Vc[i][0] = tt[i][0] - tt[i][2];
            Vc[i][1] = tt[i][1] + tt[i][2];
            Vc[i][2] = tt[i][2] - tt[i][1];
            Vc[i][3] = tt[i][1] - tt[i][3];
        }
    }
    {
        float tt[4][4];
#pragma unroll
        for (int j = 0; j < 4; j++) {
            tt[0][j] = ds[0][j] - ds[2][j];
            tt[1][j] = ds[1][j] + ds[2][j];
            tt[2][j] = ds[2][j] - ds[1][j];
            tt[3][j] = ds[1][j] - ds[3][j];
        }
#pragma unroll
        for (int i = 0; i < 4; i++) {
            Vs[i][0] = tt[i][0] - tt[i][2];
            Vs[i][1] = tt[i][1] + tt[i][2];
            Vs[i][2] = tt[i][2] - tt[i][1];
            Vs[i][3] = tt[i][1] - tt[i][3];
        }
    }
#pragma unroll
    for (int i = 0; i < 4; i++)
#pragma unroll
        for (int j = 0; j < 4; j++) {
            float* base = g_V + (size_t)(i * 4 + j) * KW * MW;
            base[(size_t)(2 * ci)     * MW + m] = Vc[i][j];
            base[(size_t)(2 * ci + 1) * MW + m] = Vs[i][j];
        }
}

/* ---------- batched GEMM: M_xi = V_xi^T x U_xi, f32x2 accum ---------- */
__global__ __launch_bounds__(GTH) void wino_gemm() {
    __shared__ __align__(16) float As[3][BK][BM];
    __shared__ __align__(16) u64   Bs[3][BK][BN];
    const int tid = threadIdx.x;
    const int mb = blockIdx.x * BM;
    const int nb = blockIdx.y * BN;
    const int xi = blockIdx.z;
    const float* Ap = g_V + (size_t)xi * KW * MW;
    const u64*   Bp = g_U + (size_t)xi * KW * NW;
    const int m0 = (tid & 15) * 4;
    const int n0 = (tid >> 4) * 8;

    u64 acc[4][8];
#pragma unroll
    for (int i = 0; i < 4; i++)
#pragma unroll
        for (int j = 0; j < 8; j++) acc[i][j] = 0ULL;

    auto load_stage = [&](int kt, int s) {
#pragma unroll
        for (int u = 0; u < 2; u++) {          /* A: 256 x 16B */
            int cch = u * GTH + tid;
            int r = cch >> 4, col = cch & 15;
            cpa16(&As[s][r][col * 4], Ap + (size_t)(kt * BK + r) * MW + mb + col * 4);
        }
#pragma unroll
        for (int u = 0; u < 4; u++) {          /* B: 512 x 16B */
            int cch = u * GTH + tid;
            int r = cch >> 5, col = cch & 31;
            cpa16(&Bs[s][r][col * 2], Bp + (size_t)(kt * BK + r) * NW + nb + col * 2);
        }
    };

    load_stage(0, 0);
    asm volatile("cp.async.commit_group;" ::: "memory");
    load_stage(1, 1);
    asm volatile("cp.async.commit_group;" ::: "memory");

#pragma unroll 1
    for (int kt = 0; kt < NKT; kt++) {
        if (kt + 2 < NKT) load_stage(kt + 2, (kt + 2) % 3);
        asm volatile("cp.async.commit_group;" ::: "memory");
        asm volatile("cp.async.wait_group 2;" ::: "memory");
        __syncthreads();
        const int s = kt % 3;
#pragma unroll
        for (int kk = 0; kk < BK; kk++) {
            float4 a = *(const float4*)&As[s][kk][m0];
            u64 bfr[8];
            const u64* bp = &Bs[s][kk][n0];
#pragma unroll
            for (int j = 0; j < 8; j++) bfr[j] = bp[j];
            u64 av;
            av = bcast2(a.x);
#pragma unroll
            for (int j = 0; j < 8; j++) fma2(acc[0][j], av, bfr[j]);
            av = bcast2(a.y);
#pragma unroll
            for (int j = 0; j < 8; j++) fma2(acc[1][j], av, bfr[j]);
            av = bcast2(a.z);
#pragma unroll
            for (int j = 0; j < 8; j++) fma2(acc[2][j], av, bfr[j]);
            av = bcast2(a.w);
#pragma unroll
            for (int j = 0; j < 8; j++) fma2(acc[3][j], av, bfr[j]);
        }
        __syncthreads();
    }

    u64* Mp = g_M + (size_t)xi * NW * MW;
#pragma unroll
    for (int j = 0; j < 8; j++) {
        u64* row = Mp + (size_t)(nb + n0 + j) * MW + mb + m0;
#pragma unroll
        for (int i = 0; i < 4; i++) row[i] = acc[i][j];
    }
}

/* ---------- output transform: Y = A^T M A (packed), atan2, store ---------- */
__global__ void wino_out(float* __restrict__ out) {
    int m = blockIdx.x * 256 + threadIdx.x;    /* grid.x = 49 */
    int n = blockIdx.y;                        /* cout 0..255 */
    u64 Mv[4][4];
#pragma unroll
    for (int i = 0; i < 4; i++)
#pragma unroll
        for (int j = 0; j < 4; j++)
            Mv[i][j] = g_M[(size_t)(i * 4 + j) * NW * MW + (size_t)n * MW + m];

    u64 t0[4], t1[4];
#pragma unroll
    for (int j = 0; j < 4; j++) {
        t0[j] = add2(add2(Mv[0][j], Mv[1][j]), Mv[2][j]);
        t1[j] = sub2(sub2(Mv[1][j], Mv[2][j]), Mv[3][j]);
    }
    u64 y00 = add2(add2(t0[0], t0[1]), t0[2]);
    u64 y01 = sub2(sub2(t0[1], t0[2]), t0[3]);
    u64 y10 = add2(add2(t1[0], t1[1]), t1[2]);
    u64 y11 = sub2(sub2(t1[1], t1[2]), t1[3]);

    int b  = m / TILES;
    int t  = m - b * TILES;
    int ty = t / 28, tx = t - (t / 28) * 28;
    float* ob = out + ((size_t)b * COUT + n) * HWHW + (2 * ty) * HW + 2 * tx;
    float re, im;
    unpack2(y00, re, im); ob[0]      = atan2f(im, re);
    unpack2(y01, re, im); ob[1]      = atan2f(im, re);
    unpack2(y10, re, im); ob[HW]     = atan2f(im, re);
    unpack2(y11, re, im); ob[HW + 1] = atan2f(im, re);
}

/* ---------- launch ---------- */
extern "C" void kernel_launch(void* const* d_in, const int* in_sizes, int n_in,
                              void* d_out, int out_size) {
    const float* x     = (const float*)d_in[0];
    const float* probe = (const float*)d_in[1];
    const float* oang  = (const float*)d_in[2];
    float* out = (float*)d_out;

    prep_input_kernel<<<(B_ * CIN * HWHW + 255) / 256, 256>>>(x);
    wino_wprep<<<(KW * NW) / 256, 256>>>(probe, oang);
    {
        dim3 g(MW / 256, CIN);
        wino_vprep<<<g, 256>>>();
    }
    {
        dim3 g(MW / BM, NW / BN, 16);          /* (196, 4, 16) */
        wino_gemm<<<g, GTH>>>();
    }
    {
        dim3 g(MW / 256, NW);
        wino_out<<<g, 256>>>(out);
    }
}